// round 1
// baseline (speedup 1.0000x reference)
#include <cuda_runtime.h>

#define BATCH  8
#define SEQ    1024
#define DMODEL 256
#define NHD    8
#define DKH    32

// ---------------- scratch (device globals; no allocations) ----------------
__device__ float g_q[(size_t)BATCH * SEQ * DMODEL];          // [B,S,D] (head-interleaved)
__device__ float g_k[(size_t)BATCH * SEQ * DMODEL];
__device__ float g_v[(size_t)BATCH * SEQ * DMODEL];
__device__ float g_scores[(size_t)BATCH * NHD * SEQ * SEQ];  // 268 MB
__device__ float g_ctx[(size_t)BATCH * SEQ * DMODEL];
__device__ float g_tmp[(size_t)BATCH * SEQ * DMODEL];
__device__ unsigned short g_idx[SEQ * SEQ];                  // di*16 + dir
__device__ float g_comb[NHD * 960];                          // per-head bias table

// ---------------- spatial index precompute ----------------
__global__ void comb_kernel(const float* __restrict__ dist_bias,
                            const float* __restrict__ dir_bias) {
    int t = blockIdx.x * 256 + threadIdx.x;
    if (t < NHD * 960) {
        int h = t / 960, r = t % 960;
        int di = r >> 4, dr = r & 15;
        g_comb[t] = dist_bias[di * NHD + h] + dir_bias[dr * NHD + h];
    }
}

__global__ void idx_kernel() {
    int e = blockIdx.x * 256 + threadIdx.x;   // grid 4096 blocks covers 1M
    int i = e >> 10, j = e & 1023;
    int h1 = i >> 5, w1 = i & 31, h2 = j >> 5, w2 = j & 31;
    int dh = h2 - h1, dw = w2 - w1;
    int n = dh * dh + dw * dw;
    int di = (int)sqrtf((float)n);
    if (di > 59) di = 59;
    // direction bin = sector of (ex,ey)=(-dw,-dh) in [0,2pi)/16, floor, ties exact
    int ex = -dw, ey = -dh, dir;
    if (ey == 0)            dir = (ex >= 0) ? 0 : 8;    // includes (0,0) -> 0
    else if (ex == 0)       dir = (ey > 0) ? 4 : 12;
    else if (ex == ey)      dir = (ex > 0) ? 2 : 10;
    else if (ex == -ey)     dir = (ex > 0) ? 14 : 6;
    else {
        float a = atan2f((float)ey, (float)ex);
        if (a < 0.0f) a += 6.28318530717958647692f;
        dir = (int)(a * 2.54647908947032537164f);       // * 8/pi
        if (dir > 15) dir = 15;
    }
    g_idx[e] = (unsigned short)(di * 16 + dir);
}

// ---------------- 128x128x32 fp32 GEMM core:  C = A(MxK) * B(NxK)^T ----------------
__device__ __forceinline__ void gemm_tile_nt(
    const float* __restrict__ gA, const float* __restrict__ gB,
    int lda, int ldb, int m0, int n0, int K,
    float (&acc)[8][8], float (*As)[132], float (*Bs)[132])
{
    const int tid = threadIdx.x;
    const int tx  = tid & 15, ty = tid >> 4;
    const int lr  = tid >> 3;            // 0..31
    const int lc  = (tid & 7) * 4;       // 0..28

    for (int kt = 0; kt < K; kt += 32) {
#pragma unroll
        for (int rr = 0; rr < 4; rr++) {
            int row = lr + rr * 32;      // 0..127
            float4 av = *(const float4*)(gA + (size_t)(m0 + row) * lda + kt + lc);
            As[lc + 0][row] = av.x; As[lc + 1][row] = av.y;
            As[lc + 2][row] = av.z; As[lc + 3][row] = av.w;
            float4 bv = *(const float4*)(gB + (size_t)(n0 + row) * ldb + kt + lc);
            Bs[lc + 0][row] = bv.x; Bs[lc + 1][row] = bv.y;
            Bs[lc + 2][row] = bv.z; Bs[lc + 3][row] = bv.w;
        }
        __syncthreads();
#pragma unroll
        for (int kk = 0; kk < 32; kk++) {
            float4 a0 = *(const float4*)&As[kk][ty * 8];
            float4 a1 = *(const float4*)&As[kk][ty * 8 + 4];
            float4 b0 = *(const float4*)&Bs[kk][tx * 8];
            float4 b1 = *(const float4*)&Bs[kk][tx * 8 + 4];
            float a[8] = {a0.x, a0.y, a0.z, a0.w, a1.x, a1.y, a1.z, a1.w};
            float b[8] = {b0.x, b0.y, b0.z, b0.w, b1.x, b1.y, b1.z, b1.w};
#pragma unroll
            for (int i2 = 0; i2 < 8; i2++)
#pragma unroll
                for (int j2 = 0; j2 < 8; j2++)
                    acc[i2][j2] += a[i2] * b[j2];
        }
        __syncthreads();
    }
}

// ---------------- QKV projection: out = x @ W^T + b, layout [B,S,D] ----------------
__global__ __launch_bounds__(256) void proj_kernel(
    const float* __restrict__ x,
    const float* __restrict__ w0, const float* __restrict__ w1, const float* __restrict__ w2,
    const float* __restrict__ b0, const float* __restrict__ b1, const float* __restrict__ b2)
{
    __shared__ __align__(16) float As[32][132];
    __shared__ __align__(16) float Bs[32][132];
    int z = blockIdx.z;
    const float* W  = (z == 0) ? w0 : ((z == 1) ? w1 : w2);
    const float* bi = (z == 0) ? b0 : ((z == 1) ? b1 : b2);
    float* out      = (z == 0) ? g_q : ((z == 1) ? g_k : g_v);

    int m0 = blockIdx.y * 128, n0 = blockIdx.x * 128;
    float acc[8][8] = {};
    gemm_tile_nt(x, W, DMODEL, DMODEL, m0, n0, DMODEL, acc, As, Bs);

    int tx = threadIdx.x & 15, ty = threadIdx.x >> 4;
#pragma unroll
    for (int i = 0; i < 8; i++) {
        size_t m = (size_t)(m0 + ty * 8 + i);
        int n = n0 + tx * 8;
        float4 o0 = {acc[i][0] + bi[n+0], acc[i][1] + bi[n+1], acc[i][2] + bi[n+2], acc[i][3] + bi[n+3]};
        float4 o1 = {acc[i][4] + bi[n+4], acc[i][5] + bi[n+5], acc[i][6] + bi[n+6], acc[i][7] + bi[n+7]};
        *(float4*)(out + m * DMODEL + n)     = o0;
        *(float4*)(out + m * DMODEL + n + 4) = o1;
    }
}

// ---------------- scores = scale * q @ k^T  (per b,h) ----------------
__global__ __launch_bounds__(256) void qk_kernel() {
    __shared__ __align__(16) float As[32][132];
    __shared__ __align__(16) float Bs[32][132];
    int bh = blockIdx.z;                 // b*8+h
    int b = bh >> 3, h = bh & 7;
    const float* A = g_q + (size_t)b * SEQ * DMODEL + h * DKH;
    const float* B = g_k + (size_t)b * SEQ * DMODEL + h * DKH;
    float* C = g_scores + (size_t)bh * SEQ * SEQ;

    int m0 = blockIdx.y * 128, n0 = blockIdx.x * 128;
    float acc[8][8] = {};
    gemm_tile_nt(A, B, DMODEL, DMODEL, m0, n0, DKH, acc, As, Bs);

    const float scale = 0.17677669529663688f;  // 1/sqrt(32)
    int tx = threadIdx.x & 15, ty = threadIdx.x >> 4;
#pragma unroll
    for (int i = 0; i < 8; i++) {
        size_t m = (size_t)(m0 + ty * 8 + i);
        float4 o0 = {acc[i][0]*scale, acc[i][1]*scale, acc[i][2]*scale, acc[i][3]*scale};
        float4 o1 = {acc[i][4]*scale, acc[i][5]*scale, acc[i][6]*scale, acc[i][7]*scale};
        *(float4*)(C + m * SEQ + n0 + tx * 8)     = o0;
        *(float4*)(C + m * SEQ + n0 + tx * 8 + 4) = o1;
    }
}

// ---------------- dual softmax: biased -> attn (in place), plain -> attn_w mean ----------------
__device__ __forceinline__ float warp_red_max(float v) {
#pragma unroll
    for (int o = 16; o; o >>= 1) v = fmaxf(v, __shfl_xor_sync(0xffffffffu, v, o));
    return v;
}
__device__ __forceinline__ float warp_red_sum(float v) {
#pragma unroll
    for (int o = 16; o; o >>= 1) v += __shfl_xor_sync(0xffffffffu, v, o);
    return v;
}
template <bool IS_MAX>
__device__ __forceinline__ void block_red2(float& a, float& b, float* redA, float* redB) {
    a = IS_MAX ? warp_red_max(a) : warp_red_sum(a);
    b = IS_MAX ? warp_red_max(b) : warp_red_sum(b);
    int w = threadIdx.x >> 5, l = threadIdx.x & 31;
    __syncthreads();
    if (l == 0) { redA[w] = a; redB[w] = b; }
    __syncthreads();
    float ra = redA[0], rb = redB[0];
#pragma unroll
    for (int k = 1; k < 8; k++) {
        if (IS_MAX) { ra = fmaxf(ra, redA[k]); rb = fmaxf(rb, redB[k]); }
        else        { ra += redA[k];           rb += redB[k]; }
    }
    a = ra; b = rb;
}

__global__ __launch_bounds__(256) void softmax_kernel(float* __restrict__ attn_w) {
    __shared__ float redA[8], redB[8];
    int blk = blockIdx.x;                // 0..8191
    int b = blk >> 10, i = blk & 1023;
    int tid = threadIdx.x;

    ushort4 iv = *(const ushort4*)(g_idx + (size_t)i * SEQ + tid * 4);
    unsigned short idx4[4] = {iv.x, iv.y, iv.z, iv.w};
    float accw[4] = {0.f, 0.f, 0.f, 0.f};

    for (int h = 0; h < NHD; h++) {
        float* srow = g_scores + ((size_t)((b * NHD + h) * SEQ + i)) * SEQ;
        float4 sv = *(const float4*)(srow + tid * 4);
        float s[4] = {sv.x, sv.y, sv.z, sv.w};
        const float* comb = g_comb + h * 960;
        float sb[4];
#pragma unroll
        for (int t = 0; t < 4; t++) sb[t] = s[t] + __ldg(comb + idx4[t]);

        float mb = fmaxf(fmaxf(sb[0], sb[1]), fmaxf(sb[2], sb[3]));
        float mp = fmaxf(fmaxf(s[0], s[1]), fmaxf(s[2], s[3]));
        block_red2<true>(mb, mp, redA, redB);

        float eb[4], ep[4], Zb = 0.f, Zp = 0.f;
#pragma unroll
        for (int t = 0; t < 4; t++) {
            eb[t] = __expf(sb[t] - mb); Zb += eb[t];
            ep[t] = __expf(s[t]  - mp); Zp += ep[t];
        }
        block_red2<false>(Zb, Zp, redA, redB);

        float ib = 1.0f / Zb;
        float4 ov = {eb[0] * ib, eb[1] * ib, eb[2] * ib, eb[3] * ib};
        *(float4*)(srow + tid * 4) = ov;
        float ip = 0.125f / Zp;
#pragma unroll
        for (int t = 0; t < 4; t++) accw[t] += ep[t] * ip;
    }
    float4 wv4 = {accw[0], accw[1], accw[2], accw[3]};
    *(float4*)(attn_w + ((size_t)(b * SEQ + i)) * SEQ + tid * 4) = wv4;
}

// ---------------- ctx = attn @ v  (2 heads per block), out [B,S,D] ----------------
__global__ __launch_bounds__(256) void pv_kernel() {
    __shared__ __align__(16) float As[2][32][68];
    __shared__ __align__(16) float Vs[32][72];
    int b = blockIdx.z, hp = blockIdx.y, i0 = blockIdx.x * 64;
    int tid = threadIdx.x, tx = tid & 15, ty = tid >> 4;
    int lr = tid >> 3, lc = (tid & 7) * 4;
    float acc[4][4] = {};

    for (int jt = 0; jt < SEQ; jt += 32) {
#pragma unroll
        for (int hl = 0; hl < 2; hl++) {
            int h = hp * 2 + hl;
            const float* ap = g_scores + (size_t)(b * NHD + h) * SEQ * SEQ;
#pragma unroll
            for (int rr = 0; rr < 2; rr++) {
                int row = lr + rr * 32;      // 0..63
                float4 av = *(const float4*)(ap + (size_t)(i0 + row) * SEQ + jt + lc);
                As[hl][lc + 0][row] = av.x; As[hl][lc + 1][row] = av.y;
                As[hl][lc + 2][row] = av.z; As[hl][lc + 3][row] = av.w;
            }
            const float* vp = g_v + (size_t)b * SEQ * DMODEL + h * DKH;
            float4 vv = *(const float4*)(vp + (size_t)(jt + lr) * DMODEL + lc);
            *(float4*)&Vs[lr][hl * 32 + lc] = vv;
        }
        __syncthreads();
        int hl = tx >> 3;
#pragma unroll
        for (int kk = 0; kk < 32; kk++) {
            float4 a4 = *(const float4*)&As[hl][kk][ty * 4];
            float4 b4 = *(const float4*)&Vs[kk][tx * 4];
            float a[4] = {a4.x, a4.y, a4.z, a4.w};
            float bb[4] = {b4.x, b4.y, b4.z, b4.w};
#pragma unroll
            for (int ri = 0; ri < 4; ri++)
#pragma unroll
                for (int ci = 0; ci < 4; ci++) acc[ri][ci] += a[ri] * bb[ci];
        }
        __syncthreads();
    }
#pragma unroll
    for (int ri = 0; ri < 4; ri++) {
        size_t m = (size_t)(b * SEQ + i0 + ty * 4 + ri);
        float4 o = {acc[ri][0], acc[ri][1], acc[ri][2], acc[ri][3]};
        *(float4*)(g_ctx + m * DMODEL + hp * 64 + tx * 4) = o;
    }
}

// ---------------- out-proj + residual ----------------
__global__ __launch_bounds__(256) void outproj_kernel(
    const float* __restrict__ x, const float* __restrict__ wo, const float* __restrict__ bo)
{
    __shared__ __align__(16) float As[32][132];
    __shared__ __align__(16) float Bs[32][132];
    int m0 = blockIdx.y * 128, n0 = blockIdx.x * 128;
    float acc[8][8] = {};
    gemm_tile_nt(g_ctx, wo, DMODEL, DMODEL, m0, n0, DMODEL, acc, As, Bs);

    int tx = threadIdx.x & 15, ty = threadIdx.x >> 4;
#pragma unroll
    for (int i = 0; i < 8; i++) {
        size_t m = (size_t)(m0 + ty * 8 + i);
        int n = n0 + tx * 8;
        float4 x0 = *(const float4*)(x + m * DMODEL + n);
        float4 x1 = *(const float4*)(x + m * DMODEL + n + 4);
        float4 o0 = {acc[i][0] + bo[n+0] + x0.x, acc[i][1] + bo[n+1] + x0.y,
                     acc[i][2] + bo[n+2] + x0.z, acc[i][3] + bo[n+3] + x0.w};
        float4 o1 = {acc[i][4] + bo[n+4] + x1.x, acc[i][5] + bo[n+5] + x1.y,
                     acc[i][6] + bo[n+6] + x1.z, acc[i][7] + bo[n+7] + x1.w};
        *(float4*)(g_tmp + m * DMODEL + n)     = o0;
        *(float4*)(g_tmp + m * DMODEL + n + 4) = o1;
    }
}

// ---------------- LayerNorm ----------------
__global__ __launch_bounds__(256) void ln_kernel(
    const float* __restrict__ lng, const float* __restrict__ lnb, float* __restrict__ y)
{
    __shared__ float redA[8], redB[8];
    size_t m = blockIdx.x;
    int tid = threadIdx.x;
    float v = g_tmp[m * DMODEL + tid];
    float s = v, dummy = 0.f;
    block_red2<false>(s, dummy, redA, redB);
    float mu = s * (1.0f / DMODEL);
    float d = v - mu;
    float sq = d * d; dummy = 0.f;
    block_red2<false>(sq, dummy, redA, redB);
    float var = sq * (1.0f / DMODEL);
    y[m * DMODEL + tid] = d * rsqrtf(var + 1e-5f) * lng[tid] + lnb[tid];
}

// ---------------- launch ----------------
extern "C" void kernel_launch(void* const* d_in, const int* in_sizes, int n_in,
                              void* d_out, int out_size) {
    const float* x    = (const float*)d_in[0];
    const float* wq   = (const float*)d_in[1];
    const float* bq   = (const float*)d_in[2];
    const float* wk   = (const float*)d_in[3];
    const float* bk   = (const float*)d_in[4];
    const float* wv   = (const float*)d_in[5];
    const float* bv   = (const float*)d_in[6];
    const float* wo   = (const float*)d_in[7];
    const float* bo   = (const float*)d_in[8];
    const float* lng  = (const float*)d_in[9];
    const float* lnb  = (const float*)d_in[10];
    const float* dist = (const float*)d_in[11];
    const float* dirb = (const float*)d_in[12];

    float* y_out  = (float*)d_out;
    float* aw_out = y_out + (size_t)BATCH * SEQ * DMODEL;   // y first, then attn_w

    comb_kernel<<<30, 256>>>(dist, dirb);
    idx_kernel<<<4096, 256>>>();
    proj_kernel<<<dim3(2, 64, 3), 256>>>(x, wq, wk, wv, bq, bk, bv);
    qk_kernel<<<dim3(8, 8, 64), 256>>>();
    softmax_kernel<<<8192, 256>>>(aw_out);
    pv_kernel<<<dim3(16, 4, 8), 256>>>();
    outproj_kernel<<<dim3(2, 64, 1), 256>>>(x, wo, bo);
    ln_kernel<<<8192, 256>>>(lng, lnb, y_out);
}

// round 2
// speedup vs baseline: 1.4703x; 1.4703x over previous
#include <cuda_runtime.h>

#define BATCH  8
#define SEQ    1024
#define DMODEL 256
#define NHD    8
#define DKH    32

// ---------------- scratch (device globals; no allocations) ----------------
__device__ float g_q[(size_t)BATCH * SEQ * DMODEL];
__device__ float g_k[(size_t)BATCH * SEQ * DMODEL];
__device__ float g_v[(size_t)BATCH * SEQ * DMODEL];
__device__ float g_scores[(size_t)BATCH * NHD * SEQ * SEQ];  // 268 MB
__device__ float g_ctx[(size_t)BATCH * SEQ * DMODEL];
__device__ float g_tmp[(size_t)BATCH * SEQ * DMODEL];
__device__ unsigned short g_idx[SEQ * SEQ];
__device__ float g_comb[NHD * 960];

// ---------------- tf32 mma helpers ----------------
__device__ __forceinline__ unsigned f2tf(float f) {
    unsigned u;
    asm("cvt.rna.tf32.f32 %0, %1;" : "=r"(u) : "f"(f));
    return u;
}
__device__ __forceinline__ void mma_tf32(float* d, const unsigned* a, const unsigned* b) {
    asm volatile(
        "mma.sync.aligned.m16n8k8.row.col.f32.tf32.tf32.f32 "
        "{%0,%1,%2,%3}, {%4,%5,%6,%7}, {%8,%9}, {%0,%1,%2,%3};"
        : "+f"(d[0]), "+f"(d[1]), "+f"(d[2]), "+f"(d[3])
        : "r"(a[0]), "r"(a[1]), "r"(a[2]), "r"(a[3]), "r"(b[0]), "r"(b[1]));
}

// ---------------- spatial index precompute ----------------
__global__ void comb_kernel(const float* __restrict__ dist_bias,
                            const float* __restrict__ dir_bias) {
    int t = blockIdx.x * 256 + threadIdx.x;
    if (t < NHD * 960) {
        int h = t / 960, r = t % 960;
        int di = r >> 4, dr = r & 15;
        g_comb[t] = dist_bias[di * NHD + h] + dir_bias[dr * NHD + h];
    }
}

__global__ void idx_kernel() {
    int e = blockIdx.x * 256 + threadIdx.x;
    int i = e >> 10, j = e & 1023;
    int h1 = i >> 5, w1 = i & 31, h2 = j >> 5, w2 = j & 31;
    int dh = h2 - h1, dw = w2 - w1;
    int n = dh * dh + dw * dw;
    int di = (int)sqrtf((float)n);
    if (di > 59) di = 59;
    int ex = -dw, ey = -dh, dir;
    if (ey == 0)            dir = (ex >= 0) ? 0 : 8;
    else if (ex == 0)       dir = (ey > 0) ? 4 : 12;
    else if (ex == ey)      dir = (ex > 0) ? 2 : 10;
    else if (ex == -ey)     dir = (ex > 0) ? 14 : 6;
    else {
        float a = atan2f((float)ey, (float)ex);
        if (a < 0.0f) a += 6.28318530717958647692f;
        dir = (int)(a * 2.54647908947032537164f);
        if (dir > 15) dir = 15;
    }
    g_idx[e] = (unsigned short)(di * 16 + dir);
}

// ---------------- smem tile loader: 128 rows x 32 cols, k-major [k][m] ----------------
__device__ __forceinline__ void load_tile(const float* __restrict__ g, int ld,
                                          int r0, int kt, float (*S)[132]) {
    int lr = threadIdx.x >> 3, lc = (threadIdx.x & 7) * 4;
#pragma unroll
    for (int rr = 0; rr < 4; rr++) {
        int row = lr + rr * 32;
        float4 v = *(const float4*)(g + (size_t)(r0 + row) * ld + kt + lc);
        S[lc + 0][row] = v.x; S[lc + 1][row] = v.y;
        S[lc + 2][row] = v.z; S[lc + 3][row] = v.w;
    }
}

// ---------------- tf32 GEMM core: 128x128 tile, C = A(MxK) @ B(NxK)^T ----------------
// 8 warps: warp_m = wid&3 (32 rows each), warp_n = wid>>2 (64 cols each)
__device__ __forceinline__ void gemm_core_tf32(
    const float* __restrict__ gA, const float* __restrict__ gB,
    int lda, int ldb, int m0, int n0, int K,
    float (&acc)[2][8][4], float (*As)[132], float (*Bs)[132])
{
    const int lane = threadIdx.x & 31, wid = threadIdx.x >> 5;
    const int wm = (wid & 3) * 32, wn = (wid >> 2) * 64;
    const int qr = lane >> 2, qc = lane & 3;

    for (int kt = 0; kt < K; kt += 32) {
        load_tile(gA, lda, m0, kt, As);
        load_tile(gB, ldb, n0, kt, Bs);
        __syncthreads();
#pragma unroll
        for (int kb = 0; kb < 32; kb += 8) {
            unsigned afr[2][4], bfr[8][2];
#pragma unroll
            for (int mi = 0; mi < 2; mi++) {
                int r = wm + mi * 16 + qr;
                afr[mi][0] = f2tf(As[kb + qc][r]);
                afr[mi][1] = f2tf(As[kb + qc][r + 8]);
                afr[mi][2] = f2tf(As[kb + 4 + qc][r]);
                afr[mi][3] = f2tf(As[kb + 4 + qc][r + 8]);
            }
#pragma unroll
            for (int ni = 0; ni < 8; ni++) {
                int nn = wn + ni * 8 + qr;
                bfr[ni][0] = f2tf(Bs[kb + qc][nn]);
                bfr[ni][1] = f2tf(Bs[kb + 4 + qc][nn]);
            }
#pragma unroll
            for (int mi = 0; mi < 2; mi++)
#pragma unroll
                for (int ni = 0; ni < 8; ni++)
                    mma_tf32(acc[mi][ni], afr[mi], bfr[ni]);
        }
        __syncthreads();
    }
}

// ---------------- QKV projection ----------------
__global__ __launch_bounds__(256) void proj_kernel(
    const float* __restrict__ x,
    const float* __restrict__ w0, const float* __restrict__ w1, const float* __restrict__ w2,
    const float* __restrict__ b0, const float* __restrict__ b1, const float* __restrict__ b2)
{
    __shared__ __align__(16) float As[32][132];
    __shared__ __align__(16) float Bs[32][132];
    int z = blockIdx.z;
    const float* W  = (z == 0) ? w0 : ((z == 1) ? w1 : w2);
    const float* bi = (z == 0) ? b0 : ((z == 1) ? b1 : b2);
    float* out      = (z == 0) ? g_q : ((z == 1) ? g_k : g_v);

    int m0 = blockIdx.y * 128, n0 = blockIdx.x * 128;
    float acc[2][8][4] = {};
    gemm_core_tf32(x, W, DMODEL, DMODEL, m0, n0, DMODEL, acc, As, Bs);

    const int lane = threadIdx.x & 31, wid = threadIdx.x >> 5;
    const int wm = (wid & 3) * 32, wn = (wid >> 2) * 64;
#pragma unroll
    for (int mi = 0; mi < 2; mi++)
#pragma unroll
        for (int ni = 0; ni < 8; ni++) {
            int row = m0 + wm + mi * 16 + (lane >> 2);
            int col = n0 + wn + ni * 8 + (lane & 3) * 2;
            float2 bv = *(const float2*)(bi + col);
            float2 o0 = {acc[mi][ni][0] + bv.x, acc[mi][ni][1] + bv.y};
            float2 o1 = {acc[mi][ni][2] + bv.x, acc[mi][ni][3] + bv.y};
            *(float2*)(out + (size_t)row * DMODEL + col)       = o0;
            *(float2*)(out + (size_t)(row + 8) * DMODEL + col) = o1;
        }
}

// ---------------- scores = scale * q @ k^T ----------------
__global__ __launch_bounds__(256) void qk_kernel() {
    __shared__ __align__(16) float As[32][132];
    __shared__ __align__(16) float Bs[32][132];
    int bh = blockIdx.z;
    int b = bh >> 3, h = bh & 7;
    const float* A = g_q + (size_t)b * SEQ * DMODEL + h * DKH;
    const float* B = g_k + (size_t)b * SEQ * DMODEL + h * DKH;
    float* C = g_scores + (size_t)bh * SEQ * SEQ;

    int m0 = blockIdx.y * 128, n0 = blockIdx.x * 128;
    float acc[2][8][4] = {};
    gemm_core_tf32(A, B, DMODEL, DMODEL, m0, n0, DKH, acc, As, Bs);

    const float scale = 0.17677669529663688f;
    const int lane = threadIdx.x & 31, wid = threadIdx.x >> 5;
    const int wm = (wid & 3) * 32, wn = (wid >> 2) * 64;
#pragma unroll
    for (int mi = 0; mi < 2; mi++)
#pragma unroll
        for (int ni = 0; ni < 8; ni++) {
            int row = m0 + wm + mi * 16 + (lane >> 2);
            int col = n0 + wn + ni * 8 + (lane & 3) * 2;
            float2 o0 = {acc[mi][ni][0] * scale, acc[mi][ni][1] * scale};
            float2 o1 = {acc[mi][ni][2] * scale, acc[mi][ni][3] * scale};
            *(float2*)(C + (size_t)row * SEQ + col)       = o0;
            *(float2*)(C + (size_t)(row + 8) * SEQ + col) = o1;
        }
}

// ---------------- dual softmax ----------------
__device__ __forceinline__ float warp_red_max(float v) {
#pragma unroll
    for (int o = 16; o; o >>= 1) v = fmaxf(v, __shfl_xor_sync(0xffffffffu, v, o));
    return v;
}
__device__ __forceinline__ float warp_red_sum(float v) {
#pragma unroll
    for (int o = 16; o; o >>= 1) v += __shfl_xor_sync(0xffffffffu, v, o);
    return v;
}
template <bool IS_MAX>
__device__ __forceinline__ void block_red2(float& a, float& b, float* redA, float* redB) {
    a = IS_MAX ? warp_red_max(a) : warp_red_sum(a);
    b = IS_MAX ? warp_red_max(b) : warp_red_sum(b);
    int w = threadIdx.x >> 5, l = threadIdx.x & 31;
    __syncthreads();
    if (l == 0) { redA[w] = a; redB[w] = b; }
    __syncthreads();
    float ra = redA[0], rb = redB[0];
#pragma unroll
    for (int k = 1; k < 8; k++) {
        if (IS_MAX) { ra = fmaxf(ra, redA[k]); rb = fmaxf(rb, redB[k]); }
        else        { ra += redA[k];           rb += redB[k]; }
    }
    a = ra; b = rb;
}

__global__ __launch_bounds__(256) void softmax_kernel(float* __restrict__ attn_w) {
    __shared__ float redA[8], redB[8];
    int blk = blockIdx.x;
    int b = blk >> 10, i = blk & 1023;
    int tid = threadIdx.x;

    ushort4 iv = *(const ushort4*)(g_idx + (size_t)i * SEQ + tid * 4);
    unsigned short idx4[4] = {iv.x, iv.y, iv.z, iv.w};
    float accw[4] = {0.f, 0.f, 0.f, 0.f};

    for (int h = 0; h < NHD; h++) {
        float* srow = g_scores + ((size_t)((b * NHD + h) * SEQ + i)) * SEQ;
        float4 sv = *(const float4*)(srow + tid * 4);
        float s[4] = {sv.x, sv.y, sv.z, sv.w};
        const float* comb = g_comb + h * 960;
        float sb[4];
#pragma unroll
        for (int t = 0; t < 4; t++) sb[t] = s[t] + __ldg(comb + idx4[t]);

        float mb = fmaxf(fmaxf(sb[0], sb[1]), fmaxf(sb[2], sb[3]));
        float mp = fmaxf(fmaxf(s[0], s[1]), fmaxf(s[2], s[3]));
        block_red2<true>(mb, mp, redA, redB);

        float eb[4], ep[4], Zb = 0.f, Zp = 0.f;
#pragma unroll
        for (int t = 0; t < 4; t++) {
            eb[t] = __expf(sb[t] - mb); Zb += eb[t];
            ep[t] = __expf(s[t]  - mp); Zp += ep[t];
        }
        block_red2<false>(Zb, Zp, redA, redB);

        float ib = 1.0f / Zb;
        float4 ov = {eb[0] * ib, eb[1] * ib, eb[2] * ib, eb[3] * ib};
        *(float4*)(srow + tid * 4) = ov;
        float ip = 0.125f / Zp;
#pragma unroll
        for (int t = 0; t < 4; t++) accw[t] += ep[t] * ip;
    }
    float4 wv4 = {accw[0], accw[1], accw[2], accw[3]};
    *(float4*)(attn_w + ((size_t)(b * SEQ + i)) * SEQ + tid * 4) = wv4;
}

// ---------------- ctx = attn @ v (tf32 mma, 128 rows x 32 cols per block) ----------------
__global__ __launch_bounds__(256) void pv_kernel() {
    __shared__ __align__(16) float As[32][132];
    __shared__ __align__(16) float Vs[32][36];
    int bh = blockIdx.y;
    int b = bh >> 3, h = bh & 7;
    int m0 = blockIdx.x * 128;
    const float* A = g_scores + (size_t)bh * SEQ * SEQ;
    const float* V = g_v + (size_t)b * SEQ * DMODEL + h * DKH;

    const int tid = threadIdx.x, lane = tid & 31, wid = tid >> 5;
    const int qr = lane >> 2, qc = lane & 3;
    float acc[4][4] = {};

    int vr = tid >> 3, vc = (tid & 7) * 4;

    for (int jt = 0; jt < SEQ; jt += 32) {
        load_tile(A, SEQ, m0, jt, As);
        float4 vv = *(const float4*)(V + (size_t)(jt + vr) * DMODEL + vc);
        Vs[vr][vc + 0] = vv.x; Vs[vr][vc + 1] = vv.y;
        Vs[vr][vc + 2] = vv.z; Vs[vr][vc + 3] = vv.w;
        __syncthreads();
#pragma unroll
        for (int kb = 0; kb < 32; kb += 8) {
            unsigned afr[4], bfr[4][2];
            int r = wid * 16 + qr;
            afr[0] = f2tf(As[kb + qc][r]);
            afr[1] = f2tf(As[kb + qc][r + 8]);
            afr[2] = f2tf(As[kb + 4 + qc][r]);
            afr[3] = f2tf(As[kb + 4 + qc][r + 8]);
#pragma unroll
            for (int ni = 0; ni < 4; ni++) {
                int nn = ni * 8 + qr;
                bfr[ni][0] = f2tf(Vs[kb + qc][nn]);
                bfr[ni][1] = f2tf(Vs[kb + 4 + qc][nn]);
            }
#pragma unroll
            for (int ni = 0; ni < 4; ni++)
                mma_tf32(acc[ni], afr, bfr[ni]);
        }
        __syncthreads();
    }

    int row = m0 + wid * 16 + qr;
    int col = qc * 2;
#pragma unroll
    for (int ni = 0; ni < 4; ni++) {
        float2 o0 = {acc[ni][0], acc[ni][1]};
        float2 o1 = {acc[ni][2], acc[ni][3]};
        *(float2*)(g_ctx + (size_t)(b * SEQ + row) * DMODEL + h * DKH + ni * 8 + col)       = o0;
        *(float2*)(g_ctx + (size_t)(b * SEQ + row + 8) * DMODEL + h * DKH + ni * 8 + col)   = o1;
    }
}

// ---------------- out-proj + residual ----------------
__global__ __launch_bounds__(256) void outproj_kernel(
    const float* __restrict__ x, const float* __restrict__ wo, const float* __restrict__ bo)
{
    __shared__ __align__(16) float As[32][132];
    __shared__ __align__(16) float Bs[32][132];
    int m0 = blockIdx.y * 128, n0 = blockIdx.x * 128;
    float acc[2][8][4] = {};
    gemm_core_tf32(g_ctx, wo, DMODEL, DMODEL, m0, n0, DMODEL, acc, As, Bs);

    const int lane = threadIdx.x & 31, wid = threadIdx.x >> 5;
    const int wm = (wid & 3) * 32, wn = (wid >> 2) * 64;
#pragma unroll
    for (int mi = 0; mi < 2; mi++)
#pragma unroll
        for (int ni = 0; ni < 8; ni++) {
            int row = m0 + wm + mi * 16 + (lane >> 2);
            int col = n0 + wn + ni * 8 + (lane & 3) * 2;
            float2 bv = *(const float2*)(bo + col);
            float2 x0 = *(const float2*)(x + (size_t)row * DMODEL + col);
            float2 x1 = *(const float2*)(x + (size_t)(row + 8) * DMODEL + col);
            float2 o0 = {acc[mi][ni][0] + bv.x + x0.x, acc[mi][ni][1] + bv.y + x0.y};
            float2 o1 = {acc[mi][ni][2] + bv.x + x1.x, acc[mi][ni][3] + bv.y + x1.y};
            *(float2*)(g_tmp + (size_t)row * DMODEL + col)       = o0;
            *(float2*)(g_tmp + (size_t)(row + 8) * DMODEL + col) = o1;
        }
}

// ---------------- LayerNorm ----------------
__global__ __launch_bounds__(256) void ln_kernel(
    const float* __restrict__ lng, const float* __restrict__ lnb, float* __restrict__ y)
{
    __shared__ float redA[8], redB[8];
    size_t m = blockIdx.x;
    int tid = threadIdx.x;
    float v = g_tmp[m * DMODEL + tid];
    float s = v, dummy = 0.f;
    block_red2<false>(s, dummy, redA, redB);
    float mu = s * (1.0f / DMODEL);
    float d = v - mu;
    float sq = d * d; dummy = 0.f;
    block_red2<false>(sq, dummy, redA, redB);
    float var = sq * (1.0f / DMODEL);
    y[m * DMODEL + tid] = d * rsqrtf(var + 1e-5f) * lng[tid] + lnb[tid];
}

// ---------------- launch ----------------
extern "C" void kernel_launch(void* const* d_in, const int* in_sizes, int n_in,
                              void* d_out, int out_size) {
    const float* x    = (const float*)d_in[0];
    const float* wq   = (const float*)d_in[1];
    const float* bq   = (const float*)d_in[2];
    const float* wk   = (const float*)d_in[3];
    const float* bk   = (const float*)d_in[4];
    const float* wv   = (const float*)d_in[5];
    const float* bv   = (const float*)d_in[6];
    const float* wo   = (const float*)d_in[7];
    const float* bo   = (const float*)d_in[8];
    const float* lng  = (const float*)d_in[9];
    const float* lnb  = (const float*)d_in[10];
    const float* dist = (const float*)d_in[11];
    const float* dirb = (const float*)d_in[12];

    float* y_out  = (float*)d_out;
    float* aw_out = y_out + (size_t)BATCH * SEQ * DMODEL;

    comb_kernel<<<30, 256>>>(dist, dirb);
    idx_kernel<<<4096, 256>>>();
    proj_kernel<<<dim3(2, 64, 3), 256>>>(x, wq, wk, wv, bq, bk, bv);
    qk_kernel<<<dim3(8, 8, 64), 256>>>();
    softmax_kernel<<<8192, 256>>>(aw_out);
    pv_kernel<<<dim3(8, 64), 256>>>();
    outproj_kernel<<<dim3(2, 64, 1), 256>>>(x, wo, bo);
    ln_kernel<<<8192, 256>>>(lng, lnb, y_out);
}